// round 11
// baseline (speedup 1.0000x reference)
#include <cuda_runtime.h>
#include <cuda_bf16.h>
#include <math.h>
#include <stdint.h>

// ---------------- problem constants ----------------
#define BATCH 2
#define C_IN 192
#define C3 576
#define HW 65536
#define IMG 256
#define HEADS 6
#define CH 32
#define WS 8
#define NTOK 64
#define NWIN 2048
#define NPAIR 32            // NTOK/2 token-pairs

__device__ float g_qkv1[(size_t)BATCH * C3 * HW];
// window-layout buffers, written by K2 in K3-ready form:
//   g_q / g_k : normalized bf16 token-pairs   [win][head][c][pair]
//   g_vh/g_vl : v split hi/lo bf16 token-pairs
__device__ uint32_t g_q [(size_t)NWIN * HEADS * CH * NPAIR];
__device__ uint32_t g_k [(size_t)NWIN * HEADS * CH * NPAIR];
__device__ uint32_t g_vh[(size_t)NWIN * HEADS * CH * NPAIR];
__device__ uint32_t g_vl[(size_t)NWIN * HEADS * CH * NPAIR];
__device__ float g_att[(size_t)BATCH * C_IN * HW];

// ---------------------------------------------------------------------------
// bf16 helpers (pair-packed b32: low 16 = even element, high 16 = odd)
// ---------------------------------------------------------------------------
__device__ __forceinline__ void split2(float e0, float e1, uint32_t& hp, uint32_t& lp)
{
    __nv_bfloat16 h0 = __float2bfloat16(e0);
    __nv_bfloat16 h1 = __float2bfloat16(e1);
    __nv_bfloat16 l0 = __float2bfloat16(e0 - __bfloat162float(h0));
    __nv_bfloat16 l1 = __float2bfloat16(e1 - __bfloat162float(h1));
    __nv_bfloat162 hh; hh.x = h0; hh.y = h1;
    __nv_bfloat162 ll; ll.x = l0; ll.y = l1;
    hp = *reinterpret_cast<uint32_t*>(&hh);
    lp = *reinterpret_cast<uint32_t*>(&ll);
}

__device__ __forceinline__ uint32_t pack_hi(float e0, float e1)
{
    __nv_bfloat162 hh; hh.x = __float2bfloat16(e0); hh.y = __float2bfloat16(e1);
    return *reinterpret_cast<uint32_t*>(&hh);
}

__device__ __forceinline__ void mma16816(float* d, const uint32_t* a, uint32_t b0, uint32_t b1)
{
    asm volatile(
        "mma.sync.aligned.m16n8k16.row.col.f32.bf16.bf16.f32 "
        "{%0,%1,%2,%3}, {%4,%5,%6,%7}, {%8,%9}, {%0,%1,%2,%3};"
        : "+f"(d[0]), "+f"(d[1]), "+f"(d[2]), "+f"(d[3])
        : "r"(a[0]), "r"(a[1]), "r"(a[2]), "r"(a[3]), "r"(b0), "r"(b1));
}

// ---------------------------------------------------------------------------
// K1/K4: GEMM (unchanged from R10 — proven)
// ---------------------------------------------------------------------------
__global__ __launch_bounds__(256, 2) void k_gemm_mma(
    const float* __restrict__ Wt, const float* __restrict__ Xall,
    float* __restrict__ Yall, const float* __restrict__ bias, int M)
{
    const float* X = Xall + (size_t)blockIdx.z * C_IN * HW;
    float* Y = Yall + (size_t)blockIdx.z * (size_t)M * HW;
    const int oTile = blockIdx.y * 64;
    const int pTile = blockIdx.x * 256;

    __shared__ uint32_t WsH[2][64][9], WsL[2][64][9];
    __shared__ uint32_t XsH[2][256][9], XsL[2][256][9];

    const int tid = threadIdx.x;
    const int lane = tid & 31;
    const int wid = tid >> 5;
    const int warpM = wid >> 2;
    const int warpN = wid & 3;
    const int g = lane >> 2;
    const int t = lane & 3;

    float acc[2][8][4];
#pragma unroll
    for (int im = 0; im < 2; im++)
#pragma unroll
        for (int jn = 0; jn < 8; jn++)
#pragma unroll
            for (int r = 0; r < 4; r++) acc[im][jn][r] = 0.f;

    const int wo = tid >> 2;
    const int wsub = tid & 3;

    for (int k0 = 0; k0 < 192; k0 += 32) {
        {
            const float* wptr = &Wt[(size_t)(oTile + wo) * 192 + k0 + wsub * 8];
            float4 f0 = *(const float4*)wptr;
            float4 f1 = *(const float4*)(wptr + 4);
            float f[8] = {f0.x, f0.y, f0.z, f0.w, f1.x, f1.y, f1.z, f1.w};
#pragma unroll
            for (int j = 0; j < 4; j++) {
                uint32_t hp, lp;
                split2(f[2 * j], f[2 * j + 1], hp, lp);
                int kk2 = wsub * 4 + j;
                int ch = kk2 >> 3, cc = kk2 & 7;
                WsH[ch][wo][cc] = hp;
                WsL[ch][wo][cc] = lp;
            }
        }
        {
#pragma unroll
            for (int it = 0; it < 2; it++) {
                int kp = (tid >> 5) + it * 8;
                int ch = kp >> 3, cc = kp & 7;
                const float* r0 = X + (size_t)(k0 + 2 * kp) * HW + pTile + lane;
#pragma unroll
                for (int pm = 0; pm < 8; pm++) {
                    float f0 = r0[pm * 32];
                    float f1 = r0[pm * 32 + HW];
                    uint32_t hp, lp;
                    split2(f0, f1, hp, lp);
                    XsH[ch][lane + 32 * pm][cc] = hp;
                    XsL[ch][lane + 32 * pm][cc] = lp;
                }
            }
        }
        __syncthreads();

#pragma unroll
        for (int ch = 0; ch < 2; ch++) {
            uint32_t Ah[2][4], Al[2][4];
#pragma unroll
            for (int im = 0; im < 2; im++) {
                int r0 = warpM * 32 + im * 16 + g;
                Ah[im][0] = WsH[ch][r0][t];
                Ah[im][1] = WsH[ch][r0 + 8][t];
                Ah[im][2] = WsH[ch][r0][t + 4];
                Ah[im][3] = WsH[ch][r0 + 8][t + 4];
                Al[im][0] = WsL[ch][r0][t];
                Al[im][1] = WsL[ch][r0 + 8][t];
                Al[im][2] = WsL[ch][r0][t + 4];
                Al[im][3] = WsL[ch][r0 + 8][t + 4];
            }
#pragma unroll
            for (int jn = 0; jn < 8; jn++) {
                int col = warpN * 64 + jn * 8 + g;
                uint32_t bh0 = XsH[ch][col][t], bh1 = XsH[ch][col][t + 4];
                uint32_t bl0 = XsL[ch][col][t], bl1 = XsL[ch][col][t + 4];
#pragma unroll
                for (int im = 0; im < 2; im++) {
                    mma16816(acc[im][jn], Al[im], bh0, bh1);
                    mma16816(acc[im][jn], Ah[im], bl0, bl1);
                    mma16816(acc[im][jn], Ah[im], bh0, bh1);
                }
            }
        }
        __syncthreads();
    }

#pragma unroll
    for (int im = 0; im < 2; im++) {
        int row = oTile + warpM * 32 + im * 16 + g;
        float bs0 = bias ? bias[row] : 0.f;
        float bs1 = bias ? bias[row + 8] : 0.f;
#pragma unroll
        for (int jn = 0; jn < 8; jn++) {
            int col = pTile + warpN * 64 + jn * 8 + t * 2;
            float2 r0 = make_float2(acc[im][jn][0] + bs0, acc[im][jn][1] + bs0);
            float2 r1 = make_float2(acc[im][jn][2] + bs1, acc[im][jn][3] + bs1);
            *(float2*)&Y[(size_t)row * HW + col] = r0;
            *(float2*)&Y[(size_t)(row + 8) * HW + col] = r1;
        }
    }
}

// ---------------------------------------------------------------------------
// K2: depthwise 3x3 + l2norm (q,k) + bf16 packing, writing K3-ready layouts.
// Block = 32x8 pixels of one channel-plane = 4 COMPLETE windows, so the
// 64-token norm for each (win, channel) row is computable in-block.
// ---------------------------------------------------------------------------
__global__ __launch_bounds__(256) void k_dwconv(
    const float* __restrict__ in, const float* __restrict__ wd,
    uint32_t* __restrict__ gq, uint32_t* __restrict__ gk,
    uint32_t* __restrict__ gvh, uint32_t* __restrict__ gvl)
{
    const int plane = blockIdx.z;
    const int b = plane / C3, ch3 = plane - b * C3;
    const int x0 = blockIdx.x * 32, y0 = blockIdx.y * 8;

    __shared__ float sm[10][34];
    __shared__ float red[4][8];
    __shared__ float invs[4];

    const float* P = in + (size_t)plane * HW;
    const int tx = threadIdx.x, ty = threadIdx.y;
    const int lt = ty * 32 + tx;

    for (int e = lt; e < 340; e += 256) {
        int r = e / 34, cc = e - r * 34;
        int gy = y0 - 1 + r, gx = x0 - 1 + cc;
        float v = 0.f;
        if (gy >= 0 && gy < IMG && gx >= 0 && gx < IMG) v = P[gy * IMG + gx];
        sm[r][cc] = v;
    }
    __syncthreads();

    const float* wp = wd + ch3 * 9;
    float s = wp[0] * sm[ty + 0][tx + 0] + wp[1] * sm[ty + 0][tx + 1] + wp[2] * sm[ty + 0][tx + 2]
            + wp[3] * sm[ty + 1][tx + 0] + wp[4] * sm[ty + 1][tx + 1] + wp[5] * sm[ty + 1][tx + 2]
            + wp[6] * sm[ty + 2][tx + 0] + wp[7] * sm[ty + 2][tx + 1] + wp[8] * sm[ty + 2][tx + 2];

    const int z = ch3 / 192;
    const int head = (ch3 % 192) >> 5;
    const int c = ch3 & 31;
    const int win = b * 1024 + (y0 >> 3) * 32 + (x0 >> 3) + (tx >> 3);
    const size_t idx = (((size_t)win * HEADS + head) * CH + c) * NPAIR + ty * 4 + ((tx & 7) >> 1);

    if (z < 2) {
        // 64-token l2 norm for this (win, c): 8-lane shfl + cross-warp smem
        float ss = s * s;
        ss += __shfl_xor_sync(0xffffffffu, ss, 1);
        ss += __shfl_xor_sync(0xffffffffu, ss, 2);
        ss += __shfl_xor_sync(0xffffffffu, ss, 4);
        if ((tx & 7) == 0) red[tx >> 3][ty] = ss;
        __syncthreads();
        if (ty == 0 && tx < 4) {
            float tot = 0.f;
#pragma unroll
            for (int i = 0; i < 8; i++) tot += red[tx][i];
            invs[tx] = 1.0f / fmaxf(sqrtf(tot), 1e-12f);
        }
        __syncthreads();
        float sn = s * invs[tx >> 3];
        float so = __shfl_down_sync(0xffffffffu, sn, 1);
        if (!(tx & 1)) {
            uint32_t hp = pack_hi(sn, so);
            (z == 0 ? gq : gk)[idx] = hp;
        }
    } else {
        float so = __shfl_down_sync(0xffffffffu, s, 1);
        if (!(tx & 1)) {
            uint32_t hp, lp;
            split2(s, so, hp, lp);
            gvh[idx] = hp;
            gvl[idx] = lp;
        }
    }
}

// ---------------------------------------------------------------------------
// K3: one block per window, 8 warps, loops 6 heads. q/k/v arrive pre-packed
// from K2 (no norm / split on the critical path). Cross-head uint32 prefetch.
// ---------------------------------------------------------------------------
#define SMA_MWH 0
#define SMA_MWL 8448
#define SMA_QH 16896
#define SMA_KH 21120
#define SMA_VPH 25344
#define SMA_VPL 29568
#define SMA_VTH 33792
#define SMA_VTL 38144
#define SMA_VS  42496
#define SMA_AS  42496
#define SMA_AH  51200
#define SMA_AL  53376
#define SMA_MBS 55552
#define SMA_TOTAL 55808

__global__ __launch_bounds__(256, 2) void k_attn(
    const uint32_t* __restrict__ gq, const uint32_t* __restrict__ gk,
    const uint32_t* __restrict__ gvh, const uint32_t* __restrict__ gvl,
    const float* __restrict__ temperature,
    const float* __restrict__ mlp_w, const float* __restrict__ mlp_b,
    float* __restrict__ out)
{
    extern __shared__ char smraw[];
    uint32_t* mwh = (uint32_t*)(smraw + SMA_MWH);
    uint32_t* mwl = (uint32_t*)(smraw + SMA_MWL);
    uint32_t* qh  = (uint32_t*)(smraw + SMA_QH);
    uint32_t* kh  = (uint32_t*)(smraw + SMA_KH);
    uint32_t* vph = (uint32_t*)(smraw + SMA_VPH);
    uint32_t* vpl = (uint32_t*)(smraw + SMA_VPL);
    uint32_t* vth = (uint32_t*)(smraw + SMA_VTH);
    uint32_t* vtl = (uint32_t*)(smraw + SMA_VTL);
    float*    vsf = (float*)(smraw + SMA_VS);
    float*    As  = (float*)(smraw + SMA_AS);
    uint32_t* Ahs = (uint32_t*)(smraw + SMA_AH);
    uint32_t* Als = (uint32_t*)(smraw + SMA_AL);
    float*    mbs = (float*)(smraw + SMA_MBS);

    const int winId = blockIdx.x;
    const int tid = threadIdx.x;
    const int lane = tid & 31;
    const int wid = tid >> 5;
    const int g = lane >> 2;
    const int t = lane & 3;
    const int mi = wid >> 2;
    const int ni = wid & 3;

    // mlp_w pack (once per block)
    {
        int y = tid >> 2, pp0 = (tid & 3) * 8;
        const float* p = mlp_w + y * 64 + pp0 * 2;
        float4 f0 = *(const float4*)p;
        float4 f1 = *(const float4*)(p + 4);
        float4 f2 = *(const float4*)(p + 8);
        float4 f3 = *(const float4*)(p + 12);
        float f[16] = {f0.x, f0.y, f0.z, f0.w, f1.x, f1.y, f1.z, f1.w,
                       f2.x, f2.y, f2.z, f2.w, f3.x, f3.y, f3.z, f3.w};
#pragma unroll
        for (int i = 0; i < 8; i++) {
            uint32_t hp, lp;
            split2(f[2 * i], f[2 * i + 1], hp, lp);
            mwh[y * 33 + pp0 + i] = hp;
            mwl[y * 33 + pp0 + i] = lp;
        }
    }
    if (tid < 64) mbs[tid] = mlp_b[tid];

    const int rr = tid >> 3;        // 0..31 : channel
    const int seg = tid & 7;        // 0..7  : pair segment (4 pairs)

    const int bb = winId >> 10, rem = winId & 1023;
    const int h1 = rem >> 5, w1 = rem & 31;

    // loop-carried prefetch registers (uint32, one head ahead)
    uint32_t q4[4], k4[4], vh4[4], vl4[4];
    {
        const size_t hb = ((size_t)(winId * HEADS) * CH + rr) * NPAIR + seg * 4;
        *(uint4*)q4  = *(const uint4*)(gq + hb);
        *(uint4*)k4  = *(const uint4*)(gk + hb);
        *(uint4*)vh4 = *(const uint4*)(gvh + hb);
        *(uint4*)vl4 = *(const uint4*)(gvl + hb);
    }

    for (int head = 0; head < HEADS; head++) {
        __syncthreads();   // (a) smem free from previous head

        // ---- store q/k/v packs; reconstruct fp32 v stage ----
#pragma unroll
        for (int i = 0; i < 4; i++) {
            qh[rr * 33 + seg * 4 + i] = q4[i];
            kh[rr * 33 + seg * 4 + i] = k4[i];
            vph[rr * 33 + seg * 4 + i] = vh4[i];
            vpl[rr * 33 + seg * 4 + i] = vl4[i];
        }
        {
            float e[8];
#pragma unroll
            for (int i = 0; i < 4; i++) {
                __nv_bfloat162 h2 = *reinterpret_cast<__nv_bfloat162*>(&vh4[i]);
                __nv_bfloat162 l2 = *reinterpret_cast<__nv_bfloat162*>(&vl4[i]);
                e[2 * i] = __bfloat162float(h2.x) + __bfloat162float(l2.x);
                e[2 * i + 1] = __bfloat162float(h2.y) + __bfloat162float(l2.y);
            }
            *(float4*)&vsf[rr * 68 + seg * 8] = make_float4(e[0], e[1], e[2], e[3]);
            *(float4*)&vsf[rr * 68 + seg * 8 + 4] = make_float4(e[4], e[5], e[6], e[7]);
        }
        // ---- prefetch next head ----
        if (head + 1 < HEADS) {
            const size_t hb = ((size_t)((winId * HEADS + head + 1)) * CH + rr) * NPAIR + seg * 4;
            *(uint4*)q4  = *(const uint4*)(gq + hb);
            *(uint4*)k4  = *(const uint4*)(gk + hb);
            *(uint4*)vh4 = *(const uint4*)(gvh + hb);
            *(uint4*)vl4 = *(const uint4*)(gvl + hb);
        }
        __syncthreads();   // (b)

        // ---- build v^T pairs over d ----
        {
            int x = tid >> 2;
            int dpb = tid & 3;
#pragma unroll
            for (int i = 0; i < 4; i++) {
                int dp = dpb + 4 * i;
                float e0 = vsf[(2 * dp) * 68 + x];
                float e1 = vsf[(2 * dp + 1) * 68 + x];
                uint32_t hp, lp;
                split2(e0, e1, hp, lp);
                vth[x * 17 + dp] = hp;
                vtl[x * 17 + dp] = lp;
            }
        }
        __syncthreads();   // (c)

        // ---- QK^T (hi-only) ----
        {
            float cacc[4] = {0.f, 0.f, 0.f, 0.f};
#pragma unroll
            for (int c = 0; c < 4; c++) {
                int p0 = c * 8 + t, p1 = p0 + 4;
                uint32_t A[4];
                A[0] = qh[(mi * 16 + g) * 33 + p0];
                A[1] = qh[(mi * 16 + g + 8) * 33 + p0];
                A[2] = qh[(mi * 16 + g) * 33 + p1];
                A[3] = qh[(mi * 16 + g + 8) * 33 + p1];
                uint32_t b0 = kh[(ni * 8 + g) * 33 + p0];
                uint32_t b1 = kh[(ni * 8 + g) * 33 + p1];
                mma16816(cacc, A, b0, b1);
            }
            const float temp = temperature[head];
            As[(mi * 16 + g) * 36 + ni * 8 + 2 * t] = cacc[0] * temp;
            As[(mi * 16 + g) * 36 + ni * 8 + 2 * t + 1] = cacc[1] * temp;
            As[(mi * 16 + g + 8) * 36 + ni * 8 + 2 * t] = cacc[2] * temp;
            As[(mi * 16 + g + 8) * 36 + ni * 8 + 2 * t + 1] = cacc[3] * temp;
        }
        __syncthreads();   // (d)

        // ---- softmax; emit split pairs ----
        {
            int r = tid >> 3, j0 = (tid & 7) * 4;
            float4 v4 = *(const float4*)&As[r * 36 + j0];
            float v[4] = {v4.x, v4.y, v4.z, v4.w};
            float m = fmaxf(fmaxf(v[0], v[1]), fmaxf(v[2], v[3]));
            m = fmaxf(m, __shfl_xor_sync(0xffffffffu, m, 1));
            m = fmaxf(m, __shfl_xor_sync(0xffffffffu, m, 2));
            m = fmaxf(m, __shfl_xor_sync(0xffffffffu, m, 4));
            float s = 0.f;
#pragma unroll
            for (int i = 0; i < 4; i++) { v[i] = __expf(v[i] - m); s += v[i]; }
            s += __shfl_xor_sync(0xffffffffu, s, 1);
            s += __shfl_xor_sync(0xffffffffu, s, 2);
            s += __shfl_xor_sync(0xffffffffu, s, 4);
            float inv = 1.0f / s;
            int jp = (tid & 7) * 2;
            uint32_t hp, lp;
            split2(v[0] * inv, v[1] * inv, hp, lp);
            Ahs[r * 17 + jp] = hp; Als[r * 17 + jp] = lp;
            split2(v[2] * inv, v[3] * inv, hp, lp);
            Ahs[r * 17 + jp + 1] = hp; Als[r * 17 + jp + 1] = lp;
        }
        __syncthreads();   // (e)

        // ---- A·V and V·mlp_w^T; fused epilogue ----
        {
            float oa[2][4], ga[2][4];
#pragma unroll
            for (int nt = 0; nt < 2; nt++)
#pragma unroll
                for (int r = 0; r < 4; r++) { oa[nt][r] = 0.f; ga[nt][r] = 0.f; }

#pragma unroll
            for (int c = 0; c < 2; c++) {
                int p0 = c * 8 + t, p1 = p0 + 4;
                uint32_t Ahf[4], Alf[4];
                Ahf[0] = Ahs[(mi * 16 + g) * 17 + p0];
                Ahf[1] = Ahs[(mi * 16 + g + 8) * 17 + p0];
                Ahf[2] = Ahs[(mi * 16 + g) * 17 + p1];
                Ahf[3] = Ahs[(mi * 16 + g + 8) * 17 + p1];
                Alf[0] = Als[(mi * 16 + g) * 17 + p0];
                Alf[1] = Als[(mi * 16 + g + 8) * 17 + p0];
                Alf[2] = Als[(mi * 16 + g) * 17 + p1];
                Alf[3] = Als[(mi * 16 + g + 8) * 17 + p1];
#pragma unroll
                for (int nt = 0; nt < 2; nt++) {
                    int n = (ni * 2 + nt) * 8 + g;
                    uint32_t bh0 = vth[n * 17 + p0], bh1 = vth[n * 17 + p1];
                    uint32_t bl0 = vtl[n * 17 + p0], bl1 = vtl[n * 17 + p1];
                    mma16816(oa[nt], Ahf, bl0, bl1);
                    mma16816(oa[nt], Alf, bh0, bh1);
                    mma16816(oa[nt], Ahf, bh0, bh1);
                }
            }
#pragma unroll
            for (int c = 0; c < 4; c++) {
                int p0 = c * 8 + t, p1 = p0 + 4;
                uint32_t Vh[4], Vl[4];
                Vh[0] = vph[(mi * 16 + g) * 33 + p0];
                Vh[1] = vph[(mi * 16 + g + 8) * 33 + p0];
                Vh[2] = vph[(mi * 16 + g) * 33 + p1];
                Vh[3] = vph[(mi * 16 + g + 8) * 33 + p1];
                Vl[0] = vpl[(mi * 16 + g) * 33 + p0];
                Vl[1] = vpl[(mi * 16 + g + 8) * 33 + p0];
                Vl[2] = vpl[(mi * 16 + g) * 33 + p1];
                Vl[3] = vpl[(mi * 16 + g + 8) * 33 + p1];
#pragma unroll
                for (int nt = 0; nt < 2; nt++) {
                    int n = (ni * 2 + nt) * 8 + g;
                    uint32_t bh0 = mwh[n * 33 + p0], bh1 = mwh[n * 33 + p1];
                    uint32_t bl0 = mwl[n * 33 + p0], bl1 = mwl[n * 33 + p1];
                    mma16816(ga[nt], Vh, bl0, bl1);
                    mma16816(ga[nt], Vl, bh0, bh1);
                    mma16816(ga[nt], Vh, bh0, bh1);
                }
            }
#pragma unroll
            for (int nt = 0; nt < 2; nt++) {
                int ntok = ni * 2 + nt;
                float b0 = mbs[ntok * 8 + 2 * t];
                float b1 = mbs[ntok * 8 + 2 * t + 1];
#pragma unroll
                for (int half = 0; half < 2; half++) {
                    int row = mi * 16 + g + half * 8;
                    float o0 = oa[nt][half * 2], o1 = oa[nt][half * 2 + 1];
                    float x0 = ga[nt][half * 2] + b0;
                    float x1 = ga[nt][half * 2 + 1] + b1;
                    float ge0 = 0.5f * x0 * (1.0f + erff(x0 * 0.70710678118654752f));
                    float ge1 = 0.5f * x1 * (1.0f + erff(x1 * 0.70710678118654752f));
                    size_t addr = ((((size_t)bb * C_IN + head * CH + row) * IMG
                                    + h1 * 8 + ntok) * IMG) + w1 * 8 + 2 * t;
                    *(float2*)&out[addr] = make_float2(o0 * ge0, o1 * ge1);
                }
            }
        }
    }
}

// ---------------------------------------------------------------------------
extern "C" void kernel_launch(void* const* d_in, const int* in_sizes, int n_in,
                              void* d_out, int out_size)
{
    const float* x           = (const float*)d_in[0];
    const float* w_qkv       = (const float*)d_in[1];
    const float* w_dw        = (const float*)d_in[2];
    const float* temperature = (const float*)d_in[3];
    const float* mlp_w       = (const float*)d_in[4];
    const float* mlp_b       = (const float*)d_in[5];
    const float* proj_w      = (const float*)d_in[6];
    const float* proj_b      = (const float*)d_in[7];
    float* out = (float*)d_out;

    float *qkv1, *att;
    uint32_t *gq, *gk, *gvh, *gvl;
    cudaGetSymbolAddress((void**)&qkv1, g_qkv1);
    cudaGetSymbolAddress((void**)&att, g_att);
    cudaGetSymbolAddress((void**)&gq, g_q);
    cudaGetSymbolAddress((void**)&gk, g_k);
    cudaGetSymbolAddress((void**)&gvh, g_vh);
    cudaGetSymbolAddress((void**)&gvl, g_vl);

    cudaFuncSetAttribute(k_attn, cudaFuncAttributeMaxDynamicSharedMemorySize, SMA_TOTAL);

    k_gemm_mma<<<dim3(HW / 256, C3 / 64, BATCH), 256>>>(w_qkv, x, qkv1, nullptr, C3);
    k_dwconv<<<dim3(IMG / 32, IMG / 8, BATCH * C3), dim3(32, 8)>>>(qkv1, w_dw, gq, gk, gvh, gvl);
    k_attn<<<NWIN, 256, SMA_TOTAL>>>(gq, gk, gvh, gvl, temperature, mlp_w, mlp_b, att);
    k_gemm_mma<<<dim3(HW / 256, C_IN / 64, BATCH), 256>>>(proj_w, att, out, proj_b, C_IN);
}